// round 10
// baseline (speedup 1.0000x reference)
#include <cuda_runtime.h>

#define T_LEN   750
#define NSLOT   64
#define SLOT_STRIDE 32       // 128B stride between slots

// exp(-x/2) = exp2(-x * 0.5*log2(e))
#define NEG_HALF_LOG2E (-0.7213475204444817f)

__device__ float        g_slots[NSLOT * SLOT_STRIDE];   // zero-init at load
__device__ unsigned int g_count;                        // zero-init at load

__device__ __forceinline__ float ex2_approx(float x) {
    float r;
    asm("ex2.approx.ftz.f32 %0, %1;" : "=f"(r) : "f"(x));
    return r;
}

// Skewed shared index: idx(i) = i + i/24. For lane-based access
// (i = 24*lane + m) this is 25*lane + m (+1 if m>=24): stride 25 across
// lanes -> conflict-free LDS (gcd(25,32)=1). Max index: idx(749) = 780.
__global__ __launch_bounds__(32, 16)
void ae_loss_kernel(const float* __restrict__ a0,
                    const float* __restrict__ a2,
                    float* __restrict__ out,
                    int B) {
    __shared__ float s0[784];
    __shared__ float s2[784];

    const int b    = blockIdx.x;
    const int lane = threadIdx.x;      // block == 1 warp
    const float* __restrict__ g0 = a0 + (size_t)b * T_LEN;
    const float* __restrict__ g2 = a2 + (size_t)b * T_LEN;

    // Coalesced global load -> skewed shared store (row offsets even -> float2 ok)
    {
        const float2* p0 = reinterpret_cast<const float2*>(g0);
        const float2* p2 = reinterpret_cast<const float2*>(g2);
        for (int q = lane; q < T_LEN / 2; q += 32) {     // 375 pairs
            float2 t0 = p0[q], t2 = p2[q];
            int i   = 2 * q;
            int siA = i + i / 24;
            int siB = (i + 1) + (i + 1) / 24;
            s0[siA] = t0.x; s0[siB] = t0.y;
            s2[siA] = t2.x; s2[siB] = t2.y;
        }
    }
    __syncwarp();

    // Per-lane register window: lane owns outputs [24*lane, 24*lane+24),
    // needs row values [24*lane .. 24*lane+29] (clamped at the end).
    float v0[30], v2[30];
#pragma unroll
    for (int m = 0; m < 30; m++) {
        // idx(min(24*lane+m, 749)) == min(25*lane + m + (m>=24), 780)
        int si = 25 * lane + m + (m >= 24 ? 1 : 0);
        si = si > 780 ? 780 : si;
        v0[m] = s0[si];
        v2[m] = s2[si];
    }

    float acc2a = 0.0f, acc2b = 0.0f;  // pair distance 1..2 / 3..4 (x2)
    float acc1  = 0.0f;                // pair distance 5..6        (x1)
    float nsq   = 0.0f;                // sum (a0-a2)^2

    if (lane < 31) {
        // Fast path: 24 outputs, all pairs (i, i+k) in-range (i <= 743)
#pragma unroll
        for (int c = 0; c < 24; c++) {
            const float x0 = v0[c], x2 = v2[c];
            const float d = x0 - x2;
            nsq = fmaf(d, d, nsq);
#pragma unroll
            for (int k = 1; k <= 6; k++) {
                const float e = ex2_approx(fabsf(x0 - v0[c + k]) * NEG_HALF_LOG2E);
                const float t = e * fabsf(x2 - v2[c + k]);
                if      (k <= 2) acc2a += t;
                else if (k <= 4) acc2b += t;
                else             acc1  += t;
            }
        }
    } else {
        // Lane 31: outputs 744..749; pairs need 744+c+k <= 749 -> c+k <= 5
#pragma unroll
        for (int c = 0; c < 6; c++) {
            const float x0 = v0[c], x2 = v2[c];
            const float d = x0 - x2;
            nsq = fmaf(d, d, nsq);
#pragma unroll
            for (int k = 1; k <= 6; k++) {
                if (c + k <= 5) {
                    const float e = ex2_approx(fabsf(x0 - v0[c + k]) * NEG_HALF_LOG2E);
                    const float t = e * fabsf(x2 - v2[c + k]);
                    if      (k <= 2) acc2a += t;
                    else if (k <= 4) acc2b += t;
                    else             acc1  += t;
                }
            }
        }
    }

    float wsum = fmaf(2.0f, acc2a + acc2b, acc1);

    // Clamped-boundary extras (replicates reference padding; verified exact):
    //   left : u=1..5     -> (6-u)   * term(u, 0)      [idx(u)=u, idx(0)=0]
    //   right: u=746..748 -> (u-745) * term(u, 749)    [idx(u)=u+31, idx(749)=780]
    if (lane == 0) {
#pragma unroll
        for (int u = 1; u <= 5; u++) {
            const float e = ex2_approx(fabsf(s0[u] - s0[0]) * NEG_HALF_LOG2E);
            wsum = fmaf((float)(6 - u) * e, fabsf(s2[u] - s2[0]), wsum);
        }
    } else if (lane == 1) {
#pragma unroll
        for (int u = 746; u <= 748; u++) {
            const float e = ex2_approx(fabsf(s0[u + 31] - s0[780]) * NEG_HALF_LOG2E);
            wsum = fmaf((float)(u - 745) * e, fabsf(s2[u + 31] - s2[780]), wsum);
        }
    }

    // Warp-only reduction
#pragma unroll
    for (int o = 16; o > 0; o >>= 1) {
        wsum += __shfl_down_sync(0xFFFFFFFFu, wsum, o);
        nsq  += __shfl_down_sync(0xFFFFFFFFu, nsq,  o);
    }

    int lastf = 0;
    if (lane == 0) {
        atomicAdd(&g_slots[(b & (NSLOT - 1)) * SLOT_STRIDE],
                  wsum + 0.1f * sqrtf(nsq));
        __threadfence();
        unsigned int prev = atomicAdd(&g_count, 1u);
        lastf = (prev == (unsigned int)(B - 1));
    }
    lastf = __shfl_sync(0xFFFFFFFFu, lastf, 0);

    // Last warp: reduce the 64 slots, write result, reset state for replay.
    if (lastf) {
        float v = atomicAdd(&g_slots[lane * SLOT_STRIDE], 0.0f)
                + atomicAdd(&g_slots[(lane + 32) * SLOT_STRIDE], 0.0f);
#pragma unroll
        for (int o = 16; o > 0; o >>= 1)
            v += __shfl_down_sync(0xFFFFFFFFu, v, o);
        if (lane == 0) {
            out[0] = v;
            g_count = 0u;
        }
        g_slots[lane * SLOT_STRIDE] = 0.0f;
        g_slots[(lane + 32) * SLOT_STRIDE] = 0.0f;
    }
}

extern "C" void kernel_launch(void* const* d_in, const int* in_sizes, int n_in,
                              void* d_out, int out_size) {
    const float* a0 = (const float*)d_in[0];
    const float* a2 = (const float*)d_in[1];
    float* out = (float*)d_out;

    const int B = in_sizes[0] / T_LEN;   // 4096

    ae_loss_kernel<<<B, 32>>>(a0, a2, out, B);
}

// round 12
// speedup vs baseline: 1.0249x; 1.0249x over previous
#include <cuda_runtime.h>

#define T_LEN   750
#define CH      4
#define THREADS 192          // 192*4 = 768 >= 750; 6 warps
#define NSLOT   64
#define SLOT_STRIDE 32       // 128B stride

// exp(-x/2) = exp2(-x * 0.5*log2(e))
#define NEG_HALF_LOG2E (-0.7213475204444817f)

__device__ float        g_slots[NSLOT * SLOT_STRIDE];   // zero-init at load
__device__ unsigned int g_count;                        // zero-init at load

__device__ __forceinline__ float ex2_approx(float x) {
    float r;
    asm("ex2.approx.ftz.f32 %0, %1;" : "=f"(r) : "f"(x));
    return r;
}

// Load the 10-float window for one row into registers (fast path only).
__device__ __forceinline__ void load_win(const float* __restrict__ g,
                                         int i_base, float* v) {
    const float2* p = reinterpret_cast<const float2*>(g + i_base);
#pragma unroll
    for (int q = 0; q < 5; q++) {
        float2 t = p[q];
        v[2*q] = t.x; v[2*q+1] = t.y;
    }
}

// Accumulate symmetric pair terms for CH outputs of one row (fast path).
__device__ __forceinline__ void accum_fast(const float* v0, const float* v2,
                                           float& acc2a, float& acc2b,
                                           float& acc1, float& nsq) {
#pragma unroll
    for (int c = 0; c < CH; c++) {
        const float x0 = v0[c], x2 = v2[c];
        const float d = x0 - x2;
        nsq = fmaf(d, d, nsq);
#pragma unroll
        for (int k = 1; k <= 6; k++) {
            const float e = ex2_approx(fabsf(x0 - v0[c+k]) * NEG_HALF_LOG2E);
            const float t = e * fabsf(x2 - v2[c+k]);
            if      (k <= 2) acc2a += t;
            else if (k <= 4) acc2b += t;
            else             acc1  += t;
        }
    }
}

// Tail variant with range masking (threads 186..191 only).
__device__ __forceinline__ void accum_tail(const float* __restrict__ g0,
                                           const float* __restrict__ g2,
                                           int i_base,
                                           float& acc2a, float& acc2b,
                                           float& acc1, float& nsq) {
    float v0[10], v2[10];
#pragma unroll
    for (int m = 0; m < 10; m++) {
        int idx = i_base + m;
        idx = idx > T_LEN - 1 ? T_LEN - 1 : idx;
        v0[m] = g0[idx];
        v2[m] = g2[idx];
    }
#pragma unroll
    for (int c = 0; c < CH; c++) {
        const int i = i_base + c;
        if (i < T_LEN) {
            const float x0 = v0[c], x2 = v2[c];
            const float d = x0 - x2;
            nsq = fmaf(d, d, nsq);
#pragma unroll
            for (int k = 1; k <= 6; k++) {
                if (i + k < T_LEN) {
                    const float e = ex2_approx(fabsf(x0 - v0[c+k]) * NEG_HALF_LOG2E);
                    const float t = e * fabsf(x2 - v2[c+k]);
                    if      (k <= 2) acc2a += t;
                    else if (k <= 4) acc2b += t;
                    else             acc1  += t;
                }
            }
        }
    }
}

__global__ __launch_bounds__(THREADS, 3)
void ae_loss_kernel(const float* __restrict__ a0,
                    const float* __restrict__ a2,
                    float* __restrict__ out,
                    int NB) {                       // NB = number of row-pairs
    __shared__ float rw[THREADS / 32];
    __shared__ float rnA[THREADS / 32];
    __shared__ float rnB[THREADS / 32];
    __shared__ bool  is_last;

    const int b   = blockIdx.x;                     // row pair index
    const int tid = threadIdx.x;
    const float* __restrict__ g0A = a0 + (size_t)(2*b)     * T_LEN;
    const float* __restrict__ g2A = a2 + (size_t)(2*b)     * T_LEN;
    const float* __restrict__ g0B = a0 + (size_t)(2*b + 1) * T_LEN;
    const float* __restrict__ g2B = a2 + (size_t)(2*b + 1) * T_LEN;

    const int i_base = tid * CH;
    float acc2a = 0.0f, acc2b = 0.0f, acc1 = 0.0f;
    float nsqA = 0.0f, nsqB = 0.0f;

    if (i_base < T_LEN) {
        if (i_base + 9 <= T_LEN - 1) {
            // Fast path: batch ALL loads for both rows up-front (MLP = 20)
            float v0A[10], v2A[10], v0B[10], v2B[10];
            load_win(g0A, i_base, v0A);
            load_win(g2A, i_base, v2A);
            load_win(g0B, i_base, v0B);
            load_win(g2B, i_base, v2B);
            accum_fast(v0A, v2A, acc2a, acc2b, acc1, nsqA);
            accum_fast(v0B, v2B, acc2a, acc2b, acc1, nsqB);
        } else {
            accum_tail(g0A, g2A, i_base, acc2a, acc2b, acc1, nsqA);
            accum_tail(g0B, g2B, i_base, acc2a, acc2b, acc1, nsqB);
        }
    }

    float wsum = fmaf(2.0f, acc2a + acc2b, acc1);

    // Clamped-boundary extras (8 terms per row; replicates reference padding):
    //   left : u=1..5     -> (6-u)   * term(u, 0)
    //   right: u=746..748 -> (u-745) * term(u, 749)
    if (tid < 16) {
        const float* h0 = (tid < 8) ? g0A : g0B;
        const float* h2 = (tid < 8) ? g2A : g2B;
        const int t8 = tid & 7;
        int u, p; float mult;
        if (t8 < 5) { u = t8 + 1;   p = 0;         mult = (float)(5 - t8); }
        else        { u = 741 + t8; p = T_LEN - 1; mult = (float)(t8 - 4); }
        const float e = ex2_approx(fabsf(h0[u] - h0[p]) * NEG_HALF_LOG2E);
        wsum = fmaf(mult * e, fabsf(h2[u] - h2[p]), wsum);
    }

    // Block reduction (6 warps)
#pragma unroll
    for (int o = 16; o > 0; o >>= 1) {
        wsum += __shfl_down_sync(0xFFFFFFFFu, wsum, o);
        nsqA += __shfl_down_sync(0xFFFFFFFFu, nsqA, o);
        nsqB += __shfl_down_sync(0xFFFFFFFFu, nsqB, o);
    }
    const int warp = tid >> 5, lane = tid & 31;
    if (lane == 0) { rw[warp] = wsum; rnA[warp] = nsqA; rnB[warp] = nsqB; }
    __syncthreads();

    if (tid == 0) {
        float w = rw[0], nA = rnA[0], nB = rnB[0];
#pragma unroll
        for (int q = 1; q < THREADS / 32; q++) {
            w += rw[q]; nA += rnA[q]; nB += rnB[q];
        }
        atomicAdd(&g_slots[(b & (NSLOT - 1)) * SLOT_STRIDE],
                  w + 0.1f * (sqrtf(nA) + sqrtf(nB)));
        __threadfence();
        unsigned int prev = atomicAdd(&g_count, 1u);
        is_last = (prev == (unsigned int)(NB - 1));
    }
    __syncthreads();

    // Last block: reduce slots, write result, reset state for next replay.
    if (is_last) {
        float v = 0.0f;
        if (tid < NSLOT)
            v = atomicAdd(&g_slots[tid * SLOT_STRIDE], 0.0f);  // L2-coherent read
#pragma unroll
        for (int o = 16; o > 0; o >>= 1)
            v += __shfl_down_sync(0xFFFFFFFFu, v, o);
        if (lane == 0 && warp < 2) rw[warp] = v;
        __syncthreads();
        if (tid == 0) {
            out[0] = rw[0] + rw[1];
            g_count = 0u;
        }
        __syncthreads();
        if (tid < NSLOT) g_slots[tid * SLOT_STRIDE] = 0.0f;
    }
}

extern "C" void kernel_launch(void* const* d_in, const int* in_sizes, int n_in,
                              void* d_out, int out_size) {
    const float* a0 = (const float*)d_in[0];
    const float* a2 = (const float*)d_in[1];
    float* out = (float*)d_out;

    const int B  = in_sizes[0] / T_LEN;   // 4096
    const int NB = B / 2;                 // 2048 row pairs

    ae_loss_kernel<<<NB, THREADS>>>(a0, a2, out, NB);
}